// round 1
// baseline (speedup 1.0000x reference)
#include <cuda_runtime.h>
#include <cuda_bf16.h>

// Shapes (fixed per reference):
//   x: [B=16, C=64, H=256, W=256] fp32
//   conv_w: [1,2,7,7], conv_b: [1]
// out = x * sigmoid(conv7x7(concat(mean_c(x), max_c(x))) + b)

#define B 16
#define C 64
#define HW 65536           // 256*256
#define HWf4 16384         // HW/4
#define PLANE (C * HW)     // 64*65536 = 2^22

// Scratch: __device__ globals (allocation-free rule).
__device__ float g_att[B * 2 * HW];   // [b][{avg,max}][h*256+w]  (8 MB)
__device__ float g_s[B * HW];         // sigmoid(conv) plane       (4 MB)

// ---------------------------------------------------------------------------
// K1: per-pixel channel mean + max.  One thread = 4 consecutive pixels (float4).
// Grid covers B * HW/4 = 262144 threads.
// ---------------------------------------------------------------------------
__global__ void k_reduce(const float* __restrict__ x) {
    int t = blockIdx.x * blockDim.x + threadIdx.x;        // [0, B*HWf4)
    int b  = t >> 14;                                     // / 16384
    int q4 = t & (HWf4 - 1);

    const float4* xb = reinterpret_cast<const float4*>(x + (size_t)b * PLANE);

    float4 v = xb[q4];                                    // c = 0
    float sx = v.x, sy = v.y, sz = v.z, sw = v.w;
    float mx = v.x, my = v.y, mz = v.z, mw = v.w;

#pragma unroll 8
    for (int c = 1; c < C; c++) {
        float4 u = xb[(size_t)c * HWf4 + q4];
        sx += u.x; sy += u.y; sz += u.z; sw += u.w;
        mx = fmaxf(mx, u.x); my = fmaxf(my, u.y);
        mz = fmaxf(mz, u.z); mw = fmaxf(mw, u.w);
    }

    const float inv = 1.0f / 64.0f;
    float4 avg = make_float4(sx * inv, sy * inv, sz * inv, sw * inv);
    float4 mxv = make_float4(mx, my, mz, mw);

    float4* avg_out = reinterpret_cast<float4*>(g_att + (size_t)b * 2 * HW);
    float4* max_out = reinterpret_cast<float4*>(g_att + (size_t)b * 2 * HW + HW);
    avg_out[q4] = avg;
    max_out[q4] = mxv;
}

// ---------------------------------------------------------------------------
// K2: 7x7 conv over [avg,max] (zero pad 3) + bias + sigmoid -> g_s.
// Block = 256 threads covering a 32(w) x 8(h) tile; smem-tiled halo.
// ---------------------------------------------------------------------------
#define TW 32
#define TH 8
__global__ void k_conv(const float* __restrict__ w, const float* __restrict__ bias) {
    __shared__ float s_avg[TH + 6][TW + 8];   // 14 x 40 (pad to dodge conflicts)
    __shared__ float s_max[TH + 6][TW + 8];
    __shared__ float s_w[98];
    __shared__ float s_b;

    int b  = blockIdx.z;
    int w0 = blockIdx.x * TW;
    int h0 = blockIdx.y * TH;
    int tid = threadIdx.x;

    if (tid < 98) s_w[tid] = w[tid];
    if (tid == 98 + 29) {}   // no-op
    if (tid == 0) s_b = bias[0];

    const float* avgp = g_att + (size_t)b * 2 * HW;
    const float* maxp = avgp + HW;

    for (int i = tid; i < 14 * 38; i += 256) {
        int dy = i / 38, dx = i - dy * 38;
        int hh = h0 - 3 + dy, ww = w0 - 3 + dx;
        float a = 0.f, m = 0.f;
        if (hh >= 0 && hh < 256 && ww >= 0 && ww < 256) {
            int idx = hh * 256 + ww;
            a = avgp[idx];
            m = maxp[idx];
        }
        s_avg[dy][dx] = a;
        s_max[dy][dx] = m;
    }
    __syncthreads();

    int lx = tid & (TW - 1);
    int ly = tid >> 5;

    float acc = s_b;
#pragma unroll
    for (int kh = 0; kh < 7; kh++) {
#pragma unroll
        for (int kw = 0; kw < 7; kw++) {
            acc = fmaf(s_w[kh * 7 + kw],      s_avg[ly + kh][lx + kw], acc);
            acc = fmaf(s_w[49 + kh * 7 + kw], s_max[ly + kh][lx + kw], acc);
        }
    }

    float sg = 1.0f / (1.0f + __expf(-acc));
    g_s[(size_t)b * HW + (h0 + ly) * 256 + (w0 + lx)] = sg;
}

// ---------------------------------------------------------------------------
// K3: out = x * s (s broadcast over C).  One thread = one float4.
// s plane is 4 MB total -> resident in L2 after first touch.
// ---------------------------------------------------------------------------
__global__ void k_mul(const float* __restrict__ x, float* __restrict__ out) {
    size_t t = (size_t)blockIdx.x * blockDim.x + threadIdx.x;  // [0, 2^24)
    size_t e = t << 2;                                          // element index
    int b = (int)(e >> 22);                                     // / (C*HW)
    int q = (int)(e & (HW - 1));

    float4 xv = reinterpret_cast<const float4*>(x)[t];
    float4 sv = *reinterpret_cast<const float4*>(g_s + (size_t)b * HW + q);
    xv.x *= sv.x; xv.y *= sv.y; xv.z *= sv.z; xv.w *= sv.w;
    reinterpret_cast<float4*>(out)[t] = xv;
}

// ---------------------------------------------------------------------------
extern "C" void kernel_launch(void* const* d_in, const int* in_sizes, int n_in,
                              void* d_out, int out_size) {
    const float* x  = (const float*)d_in[0];
    const float* cw = (const float*)d_in[1];
    const float* cb = (const float*)d_in[2];
    float* out = (float*)d_out;

    // K1: 262144 threads
    k_reduce<<<(B * HWf4) / 256, 256>>>(x);

    // K2: grid 8 x 32 x 16, 256 threads
    dim3 g2(256 / TW, 256 / TH, B);
    k_conv<<<g2, 256>>>(cw, cb);

    // K3: 16M float4 threads
    k_mul<<<(B * PLANE / 4) / 256, 256>>>(x, out);
}